// round 1
// baseline (speedup 1.0000x reference)
#include <cuda_runtime.h>
#include <math.h>

// Problem constants
#define Bz 32
#define Hh 512
#define Ll 2
#define Vv 10000
#define Tt 20
#define Ss 49
#define G4 2048   // 4*H

// ---------------- device scratch (no allocations allowed) ----------------
__device__ float g_keysT[Bz*Ss*Hh];     // [b][s][d]   (tanh(chan@Wk^T+bk), transposed)
__device__ float g_values[Bz*Hh*Ss];    // [b][d][s]
__device__ float g_h[Ll*Bz*Hh];         // hidden state
__device__ float g_c[Ll*Bz*Hh];         // cell state
__device__ float g_emb[Bz*Hh];          // current input embedding
__device__ float g_gpart[4*Bz*G4];      // k-split partial gate sums
__device__ float g_logits[Bz*Vv];       // contiguous logits for argmax
__device__ float g_WihT[Ll*Hh*G4];      // [l][k][j]
__device__ float g_WhhT[Ll*Hh*G4];
__device__ float g_projWT[Hh*Vv];       // [d][v]
__device__ float g_WqT[Hh*Hh];          // [k][d]
__device__ float g_hattWT[2*Hh*Hh];     // [k(1024)][d]

__device__ __forceinline__ float sigm(float x) { return 1.0f / (1.0f + expf(-x)); }

// ---------------- generic transpose: dst[c*R + r] = src[r*C + c] ----------------
__global__ void transpose_kernel(const float* __restrict__ src, float* __restrict__ dst,
                                 int R, int C) {
    int id = blockIdx.x * 256 + threadIdx.x;
    if (id >= R * C) return;
    int r = id / C, c = id - r * C;
    dst[c * R + r] = src[id];
}

// ---------------- init state ----------------
__global__ void init_kernel(const float* __restrict__ pooled,
                            const float* __restrict__ embed,
                            const int* __restrict__ sos) {
    int i = blockIdx.x * 256 + threadIdx.x;
    if (i >= Bz * Hh) return;
    int d = i & (Hh - 1);
    g_emb[i] = embed[sos[0] * Hh + d];
    float p = pooled[i];
    g_h[i] = p; g_h[Bz*Hh + i] = p;
    g_c[i] = p; g_c[Bz*Hh + i] = p;
}

// ---------------- keys / values precompute ----------------
__global__ void kv_kernel(const float* __restrict__ chan,
                          const float* __restrict__ Wk, const float* __restrict__ bk,
                          const float* __restrict__ Wv, const float* __restrict__ bv) {
    int id = blockIdx.x * 256 + threadIdx.x;
    if (id >= Bz * Hh * Ss) return;
    int s = id % Ss;
    int d = (id / Ss) & (Hh - 1);
    int b = id / (Ss * Hh);
    const float* cp  = &chan[(b * Hh + d) * Ss];
    const float* wkp = &Wk[s * Ss];
    const float* wvp = &Wv[s * Ss];
    float aK = bk[s], aV = bv[s];
#pragma unroll
    for (int k = 0; k < Ss; k++) { float c = cp[k]; aK += c * wkp[k]; aV += c * wvp[k]; }
    g_keysT[(b * Ss + s) * Hh + d] = tanhf(aK);
    g_values[(b * Hh + d) * Ss + s] = tanhf(aV);
}

// ---------------- res[:, :, 0] from <SOS> embedding (same for all b) ----------------
__global__ void t0_kernel(const float* __restrict__ projb, float* __restrict__ res) {
    int v = blockIdx.x * 256 + threadIdx.x;
    if (v >= Vv) return;
    float acc = projb[v];
    for (int d = 0; d < Hh; d++) acc += g_emb[d] * g_projWT[d * Vv + v];
    for (int b = 0; b < Bz; b++) res[b * (Vv * Tt) + v * Tt] = acc;
}

// ---------------- LSTM gate GEMM (k-split partials) ----------------
// grid (32, 4): x = 64-wide j chunk, y = 256-wide reduction slice (y<2: x-part, else h-part)
__global__ __launch_bounds__(256) void gates_kernel(int l) {
    __shared__ float sh[32 * 256];
    int tid = threadIdx.x;
    int y = blockIdx.y;
    const float* src = (y < 2) ? ((l == 0) ? g_emb : g_h) : (g_h + l * Bz * Hh);
    int off = (y & 1) * 256;
    for (int b = 0; b < 32; b++)
        sh[b * 256 + tid] = src[b * Hh + off + tid];
    __syncthreads();

    const float* WT = ((y < 2) ? g_WihT : g_WhhT) + l * Hh * G4;
    int kbase = (y & 1) * 256;
    int jl = tid & 63, bg = tid >> 6;
    int j = blockIdx.x * 64 + jl;

    float acc0=0,acc1=0,acc2=0,acc3=0,acc4=0,acc5=0,acc6=0,acc7=0;
    const float* shb = &sh[bg * 8 * 256];
#pragma unroll 4
    for (int mi = 0; mi < 256; mi += 4) {
        const float* wp = &WT[(kbase + mi) * G4 + j];
        float w0 = wp[0], w1 = wp[G4], w2 = wp[2*G4], w3 = wp[3*G4];
        float4 v0 = *(const float4*)&shb[0*256 + mi];
        float4 v1 = *(const float4*)&shb[1*256 + mi];
        float4 v2 = *(const float4*)&shb[2*256 + mi];
        float4 v3 = *(const float4*)&shb[3*256 + mi];
        float4 v4 = *(const float4*)&shb[4*256 + mi];
        float4 v5 = *(const float4*)&shb[5*256 + mi];
        float4 v6 = *(const float4*)&shb[6*256 + mi];
        float4 v7 = *(const float4*)&shb[7*256 + mi];
        acc0 += v0.x*w0 + v0.y*w1 + v0.z*w2 + v0.w*w3;
        acc1 += v1.x*w0 + v1.y*w1 + v1.z*w2 + v1.w*w3;
        acc2 += v2.x*w0 + v2.y*w1 + v2.z*w2 + v2.w*w3;
        acc3 += v3.x*w0 + v3.y*w1 + v3.z*w2 + v3.w*w3;
        acc4 += v4.x*w0 + v4.y*w1 + v4.z*w2 + v4.w*w3;
        acc5 += v5.x*w0 + v5.y*w1 + v5.z*w2 + v5.w*w3;
        acc6 += v6.x*w0 + v6.y*w1 + v6.z*w2 + v6.w*w3;
        acc7 += v7.x*w0 + v7.y*w1 + v7.z*w2 + v7.w*w3;
    }
    int bb = bg * 8;
    g_gpart[(y*32 + bb+0)*G4 + j] = acc0;
    g_gpart[(y*32 + bb+1)*G4 + j] = acc1;
    g_gpart[(y*32 + bb+2)*G4 + j] = acc2;
    g_gpart[(y*32 + bb+3)*G4 + j] = acc3;
    g_gpart[(y*32 + bb+4)*G4 + j] = acc4;
    g_gpart[(y*32 + bb+5)*G4 + j] = acc5;
    g_gpart[(y*32 + bb+6)*G4 + j] = acc6;
    g_gpart[(y*32 + bb+7)*G4 + j] = acc7;
}

// ---------------- LSTM cell update (sum partials + elementwise) ----------------
__global__ void cell_kernel(int l, const float* __restrict__ bih,
                            const float* __restrict__ bhh) {
    int b = blockIdx.x, j = threadIdx.x;
    const float* bi = &bih[l * G4];
    const float* bh = &bhh[l * G4];
    float gi = bi[j]        + bh[j];
    float gf = bi[512 + j]  + bh[512 + j];
    float gg = bi[1024 + j] + bh[1024 + j];
    float go = bi[1536 + j] + bh[1536 + j];
#pragma unroll
    for (int ks = 0; ks < 4; ks++) {
        const float* gp = &g_gpart[(ks * 32 + b) * G4];
        gi += gp[j]; gf += gp[512 + j]; gg += gp[1024 + j]; go += gp[1536 + j];
    }
    int idx = (l * Bz + b) * Hh + j;
    float c  = g_c[idx];
    float cn = sigm(gf) * c + sigm(gi) * tanhf(gg);
    g_c[idx] = cn;
    g_h[idx] = sigm(go) * tanhf(cn);
}

// ---------------- logits GEMM: out = h[1] @ projW^T + projb ----------------
// grid: ceil(V/64) blocks; block 256 = 64 v-lanes x 4 batch-groups (8 b each)
__global__ __launch_bounds__(256) void logits_kernel(const float* __restrict__ projb,
                                                     float* __restrict__ res, int t) {
    extern __shared__ float shl[];  // [32][512]
    int tid = threadIdx.x;
    const float* H1 = &g_h[Bz * Hh];
    for (int f = tid; f < Bz * Hh; f += 256) shl[f] = H1[f];
    __syncthreads();

    int vl = tid & 63, bg = tid >> 6;
    int v = blockIdx.x * 64 + vl;
    if (v >= Vv) return;

    float acc0=0,acc1=0,acc2=0,acc3=0,acc4=0,acc5=0,acc6=0,acc7=0;
    const float* shb = &shl[bg * 8 * Hh];
#pragma unroll 4
    for (int d = 0; d < Hh; d += 4) {
        const float* wp = &g_projWT[d * Vv + v];
        float w0 = wp[0], w1 = wp[Vv], w2 = wp[2*Vv], w3 = wp[3*Vv];
        float4 v0 = *(const float4*)&shb[0*Hh + d];
        float4 v1 = *(const float4*)&shb[1*Hh + d];
        float4 v2 = *(const float4*)&shb[2*Hh + d];
        float4 v3 = *(const float4*)&shb[3*Hh + d];
        float4 v4 = *(const float4*)&shb[4*Hh + d];
        float4 v5 = *(const float4*)&shb[5*Hh + d];
        float4 v6 = *(const float4*)&shb[6*Hh + d];
        float4 v7 = *(const float4*)&shb[7*Hh + d];
        acc0 += v0.x*w0 + v0.y*w1 + v0.z*w2 + v0.w*w3;
        acc1 += v1.x*w0 + v1.y*w1 + v1.z*w2 + v1.w*w3;
        acc2 += v2.x*w0 + v2.y*w1 + v2.z*w2 + v2.w*w3;
        acc3 += v3.x*w0 + v3.y*w1 + v3.z*w2 + v3.w*w3;
        acc4 += v4.x*w0 + v4.y*w1 + v4.z*w2 + v4.w*w3;
        acc5 += v5.x*w0 + v5.y*w1 + v5.z*w2 + v5.w*w3;
        acc6 += v6.x*w0 + v6.y*w1 + v6.z*w2 + v6.w*w3;
        acc7 += v7.x*w0 + v7.y*w1 + v7.z*w2 + v7.w*w3;
    }
    float pb = projb[v];
    float a[8] = {acc0,acc1,acc2,acc3,acc4,acc5,acc6,acc7};
#pragma unroll
    for (int i = 0; i < 8; i++) {
        int b = bg * 8 + i;
        float r = a[i] + pb;
        g_logits[b * Vv + v] = r;
        res[b * (Vv * Tt) + v * Tt + t] = r;
    }
}

// ---------------- argmax over logits + gather next embedding ----------------
__global__ void argmax_embed_kernel(const float* __restrict__ embed) {
    __shared__ float sv[256];
    __shared__ int   si[256];
    int b = blockIdx.x, tid = threadIdx.x;
    float best = -INFINITY; int bi = 0;
    for (int v = tid; v < Vv; v += 256) {
        float x = g_logits[b * Vv + v];
        if (x > best) { best = x; bi = v; }   // strict > keeps first occurrence
    }
    sv[tid] = best; si[tid] = bi;
    __syncthreads();
    for (int s = 128; s > 0; s >>= 1) {
        if (tid < s) {
            float ov = sv[tid + s]; int oi = si[tid + s];
            if (ov > sv[tid] || (ov == sv[tid] && oi < si[tid])) { sv[tid] = ov; si[tid] = oi; }
        }
        __syncthreads();
    }
    int widx = si[0];
    for (int d = tid; d < Hh; d += 256)
        g_emb[b * Hh + d] = embed[widx * Hh + d];
}

// ---------------- cross-attention gated hidden update (per (l,b) block) ----------------
__global__ __launch_bounds__(512) void attention_kernel(const float* __restrict__ bq,
                                                        const float* __restrict__ hattb) {
    __shared__ float sh_h[Hh], sh_q[Hh], sh_attn[Hh];
    __shared__ float sh_sc[Ss], sh_w[Ss], sh_inv;
    int tid = threadIdx.x;
    int l = blockIdx.x >> 5, b = blockIdx.x & 31;
    int base = (l * Bz + b) * Hh;
    sh_h[tid] = g_h[base + tid];
    __syncthreads();

    // q = tanh(h @ Wq^T + bq)
    {
        float acc = bq[tid];
#pragma unroll 4
        for (int k = 0; k < Hh; k += 4) {
            float4 hv = *(const float4*)&sh_h[k];
            const float* wp = &g_WqT[k * Hh + tid];
            acc += hv.x*wp[0] + hv.y*wp[Hh] + hv.z*wp[2*Hh] + hv.w*wp[3*Hh];
        }
        sh_q[tid] = tanhf(acc);
    }
    __syncthreads();

    // scores[s] = q . keys[b,:,s] / 7
    int wid = tid >> 5, lane = tid & 31;
    for (int s = wid; s < Ss; s += 16) {
        const float* kp = &g_keysT[(b * Ss + s) * Hh];
        float p = 0.f;
        for (int d = lane; d < Hh; d += 32) p += sh_q[d] * kp[d];
#pragma unroll
        for (int o = 16; o; o >>= 1) p += __shfl_down_sync(0xffffffffu, p, o);
        if (lane == 0) sh_sc[s] = p * (1.0f / 7.0f);
    }
    __syncthreads();

    if (tid < Ss) {
        float mx = sh_sc[0];
        for (int s = 1; s < Ss; s++) mx = fmaxf(mx, sh_sc[s]);
        sh_w[tid] = expf(sh_sc[tid] - mx);
    }
    __syncthreads();
    if (tid == 0) {
        float sum = 0.f;
        for (int s = 0; s < Ss; s++) sum += sh_w[s];
        sh_inv = 1.0f / sum;
    }
    __syncthreads();

    // attn[d] = sum_s w[s] * values[b,d,s]
    {
        const float* vp = &g_values[(b * Hh + tid) * Ss];
        float acc = 0.f;
#pragma unroll
        for (int s = 0; s < Ss; s++) acc += sh_w[s] * vp[s];
        sh_attn[tid] = acc * sh_inv;
    }
    __syncthreads();

    // h = tanh([attn, h] @ hattW^T + hattb)
    {
        float acc = hattb[tid];
#pragma unroll 4
        for (int k = 0; k < Hh; k += 4) {
            float4 av = *(const float4*)&sh_attn[k];
            const float* wp = &g_hattWT[k * Hh + tid];
            acc += av.x*wp[0] + av.y*wp[Hh] + av.z*wp[2*Hh] + av.w*wp[3*Hh];
        }
#pragma unroll 4
        for (int k = 0; k < Hh; k += 4) {
            float4 hv = *(const float4*)&sh_h[k];
            const float* wp = &g_hattWT[(Hh + k) * Hh + tid];
            acc += hv.x*wp[0] + hv.y*wp[Hh] + hv.z*wp[2*Hh] + hv.w*wp[3*Hh];
        }
        g_h[base + tid] = tanhf(acc);
    }
}

// ---------------- host launcher ----------------
extern "C" void kernel_launch(void* const* d_in, const int* in_sizes, int n_in,
                              void* d_out, int out_size) {
    const float* img    = (const float*)d_in[0];
    const float* pooled = (const float*)d_in[1];
    const float* embed  = (const float*)d_in[2];
    const float* Wq     = (const float*)d_in[3];
    const float* bq     = (const float*)d_in[4];
    const float* Wk     = (const float*)d_in[5];
    const float* bk     = (const float*)d_in[6];
    const float* Wv     = (const float*)d_in[7];
    const float* bv     = (const float*)d_in[8];
    const float* Wih    = (const float*)d_in[9];
    const float* Whh    = (const float*)d_in[10];
    const float* bih    = (const float*)d_in[11];
    const float* bhh    = (const float*)d_in[12];
    const float* projW  = (const float*)d_in[13];
    const float* projb  = (const float*)d_in[14];
    const float* hattW  = (const float*)d_in[15];
    const float* hattb  = (const float*)d_in[16];
    const int*   sos    = (const int*)d_in[17];
    float* res = (float*)d_out;

    void *pProjWT, *pWihT, *pWhhT, *pWqT, *pHattWT;
    cudaGetSymbolAddress(&pProjWT, g_projWT);
    cudaGetSymbolAddress(&pWihT,   g_WihT);
    cudaGetSymbolAddress(&pWhhT,   g_WhhT);
    cudaGetSymbolAddress(&pWqT,    g_WqT);
    cudaGetSymbolAddress(&pHattWT, g_hattWT);

    cudaFuncSetAttribute(logits_kernel, cudaFuncAttributeMaxDynamicSharedMemorySize,
                         Bz * Hh * (int)sizeof(float));

    // weight transposes (coalesced inner loops later)
    transpose_kernel<<<(Vv*Hh + 255)/256, 256>>>(projW, (float*)pProjWT, Vv, Hh);
    transpose_kernel<<<(G4*Hh + 255)/256, 256>>>(Wih,            (float*)pWihT,            G4, Hh);
    transpose_kernel<<<(G4*Hh + 255)/256, 256>>>(Wih + G4*Hh,    (float*)pWihT + Hh*G4,    G4, Hh);
    transpose_kernel<<<(G4*Hh + 255)/256, 256>>>(Whh,            (float*)pWhhT,            G4, Hh);
    transpose_kernel<<<(G4*Hh + 255)/256, 256>>>(Whh + G4*Hh,    (float*)pWhhT + Hh*G4,    G4, Hh);
    transpose_kernel<<<(Hh*Hh + 255)/256, 256>>>(Wq,   (float*)pWqT,    Hh, Hh);
    transpose_kernel<<<(Hh*2*Hh + 255)/256, 256>>>(hattW, (float*)pHattWT, Hh, 2*Hh);

    init_kernel<<<(Bz*Hh + 255)/256, 256>>>(pooled, embed, sos);
    kv_kernel<<<(Bz*Hh*Ss + 255)/256, 256>>>(img, Wk, bk, Wv, bv);
    t0_kernel<<<(Vv + 255)/256, 256>>>(projb, res);

    const int logits_smem = Bz * Hh * (int)sizeof(float);
    for (int t = 0; t < Tt - 1; t++) {
        gates_kernel<<<dim3(G4/64, 4), 256>>>(0);
        cell_kernel<<<Bz, Hh>>>(0, bih, bhh);
        gates_kernel<<<dim3(G4/64, 4), 256>>>(1);
        cell_kernel<<<Bz, Hh>>>(1, bih, bhh);
        logits_kernel<<<(Vv + 63)/64, 256, logits_smem>>>(projb, res, t + 1);
        argmax_embed_kernel<<<Bz, 256>>>(embed);
        attention_kernel<<<Ll*Bz, 512>>>(bq, hattb);
    }
}